// round 16
// baseline (speedup 1.0000x reference)
#include <cuda_runtime.h>

#define B 128
#define DF 2048
#define KSPLIT 64
#define KCHUNK 32           // DF / KSPLIT
#define NBLOCKS 256
#define NTHREADS 256

// Scratch (static device globals; no allocation).
__device__ float g_Gp[KSPLIT * B * B];   // split-K partial Gram (4MB)
__device__ float g_G[B * B];             // reduced Gram
__device__ float g_part[NBLOCKS];        // per-block loss partials
__device__ unsigned g_bar[2];            // monotonic barrier counters (never reset)
__device__ unsigned g_fin;               // monotonic finalize counter (never reset)

// Monotonic grid barrier: no reset across graph replays (2^32 % 256 == 0).
__device__ __forceinline__ void grid_barrier(int which) {
    __syncthreads();
    if (threadIdx.x == 0) {
        __threadfence();                                   // release
        unsigned old = atomicAdd(&g_bar[which], 1u);
        unsigned target = old - (old & (NBLOCKS - 1u)) + NBLOCKS;
        while ((int)(*(volatile unsigned*)&g_bar[which] - target) < 0) {
            __nanosleep(64);
        }
        __threadfence();                                   // acquire
    }
    __syncthreads();
}

__global__ __launch_bounds__(NTHREADS) void fused_angle_loss(
    const float* __restrict__ X, float* __restrict__ out) {

    __shared__ float smemBuf[2 * KCHUNK * 68];   // 17.4KB -> 2 CTAs/SM fit easily
    const int b = blockIdx.x;
    const int t = threadIdx.x;

    // ============================ Phase 1: split-K Gram =====================
    // block b: z = b>>2 (K chunk of 32), tile index b&3 -> 64x64 output tile.
    // 256 blocks => ~2 CTAs/SM: co-resident CTAs hide each other's memory
    // latency and barrier spin. All 4 LDG.128 issued in ONE batch.
    {
        const int z     = b >> 2;
        const int tileR = ((b >> 1) & 1) * 64;
        const int tileC = (b & 1) * 64;
        const int kBase = z * KCHUNK;

        float (*As)[68] = (float(*)[68])smemBuf;
        float (*Bs)[68] = (float(*)[68])(smemBuf + KCHUNK * 68);

        float4 va[2], vb[2];
#pragma unroll
        for (int it = 0; it < 2; it++) {         // batched: 4 independent LDG.128
            const int i   = t + it * NTHREADS;   // 0..511
            const int row = i >> 3;              // 0..63
            const int kq  = (i & 7) * 4;         // 0..28
            va[it] = *(const float4*)(X + (size_t)(tileR + row) * DF + kBase + kq);
            vb[it] = *(const float4*)(X + (size_t)(tileC + row) * DF + kBase + kq);
        }
#pragma unroll
        for (int it = 0; it < 2; it++) {
            const int i   = t + it * NTHREADS;
            const int row = i >> 3;
            const int kq  = (i & 7) * 4;
            As[kq + 0][row] = va[it].x; As[kq + 1][row] = va[it].y;
            As[kq + 2][row] = va[it].z; As[kq + 3][row] = va[it].w;
            Bs[kq + 0][row] = vb[it].x; Bs[kq + 1][row] = vb[it].y;
            Bs[kq + 2][row] = vb[it].z; Bs[kq + 3][row] = vb[it].w;
        }
        __syncthreads();

        const int r0 = (t >> 4) * 4;
        const int c0 = (t & 15) * 4;
        float acc[4][4] = {};
#pragma unroll 8
        for (int k = 0; k < KCHUNK; k++) {
            float4 a  = *(const float4*)&As[k][r0];
            float4 bb = *(const float4*)&Bs[k][c0];
            const float av[4] = {a.x, a.y, a.z, a.w};
            const float bv[4] = {bb.x, bb.y, bb.z, bb.w};
#pragma unroll
            for (int ii = 0; ii < 4; ii++)
#pragma unroll
                for (int jj = 0; jj < 4; jj++)
                    acc[ii][jj] = fmaf(av[ii], bv[jj], acc[ii][jj]);
        }

        float* dst = g_Gp + (size_t)z * (B * B);
#pragma unroll
        for (int ii = 0; ii < 4; ii++) {
            float4 v = make_float4(acc[ii][0], acc[ii][1], acc[ii][2], acc[ii][3]);
            *(float4*)&dst[(tileR + r0 + ii) * B + tileC + c0] = v;
        }
    }

    grid_barrier(0);

    // ===================== Phase 2: split-K reduce (64 layers) ==============
    // 4096 float4 outputs / 256 blocks = 16 per block. t<128: f4c = t&15,
    // z-group zg = t>>4 (0..7) sums 8 layers; t<16 combines the 8 partials
    // in fixed zg order (deterministic).
    {
        float4* part = (float4*)smemBuf;           // [8][16] float4 = 2KB
        if (t < 128) {
            const int f4c = t & 15;
            const int zg  = t >> 4;
            const int f4  = b * 16 + f4c;
            const float4* src = (const float4*)g_Gp;
            float4 s = make_float4(0.f, 0.f, 0.f, 0.f);
#pragma unroll
            for (int zz = 0; zz < 8; zz++) {
                float4 v = __ldcg(src + (size_t)(zg * 8 + zz) * 4096 + f4);
                s.x += v.x; s.y += v.y; s.z += v.z; s.w += v.w;
            }
            part[zg * 16 + f4c] = s;
        }
        __syncthreads();
        if (t < 16) {
            float4 r = part[t];
#pragma unroll
            for (int zg2 = 1; zg2 < 8; zg2++) {
                float4 v = part[zg2 * 16 + t];
                r.x += v.x; r.y += v.y; r.z += v.z; r.w += v.w;
            }
            ((float4*)g_G)[b * 16 + t] = r;
        }
    }

    grid_barrier(1);

    // ======================= Phase 3: loss (all 256 blocks) =================
    // b = group*16 + slice2; slice2 = s*2 + hh. Group g=(target,sub); pair
    // rows (j0,j1) = (16p+s, 16p+s+8) for p in [4hh, 4hh+4) \ {tgt}.
    // Threads: k = t&127, half h = t>>7 -> p = 4hh + 2h + pi, pi in {0,1}.
    {
        const int g    = b >> 4;
        const int sl   = b & 15;
        const int s    = sl >> 1;
        const int hh   = sl & 1;
        const int tgt  = g >> 1;
        const int sb   = g & 1;
        const int base = tgt * 16 + sb * 8;
        const int k    = t & 127;
        const int h    = t >> 7;

        float* sS    = smemBuf;          // [128] mean row-dot (already /8)
        float* sInv  = smemBuf + 128;    // [128] 1/norm
        float* sDiag = smemBuf + 256;    // [128] G[k][k]
        float* red   = smemBuf + 384;    // [8]
        int*   sFlag = (int*)(smemBuf + 392);

        // ---- batched loads (independent; one MLP window) ----
        float rowv[8];
        float gv0[2], gv1[2];
        float dia = 0.f;

        if (h == 0) {
#pragma unroll
            for (int i = 0; i < 8; i++) rowv[i] = __ldcg(&g_G[(base + i) * B + k]);
        } else {
            dia = __ldcg(&g_G[k * B + k]);
        }
#pragma unroll
        for (int pi = 0; pi < 2; pi++) {
            const int p  = hh * 4 + h * 2 + pi;
            const int j0 = p * 16 + s;
            gv0[pi] = __ldcg(&g_G[j0 * B + k]);         // loaded even if p==tgt
            gv1[pi] = __ldcg(&g_G[(j0 + 8) * B + k]);
        }
        __syncthreads();    // phase-2 smem reads complete before overwrite

        if (h == 0) {
            float sk = ((rowv[0] + rowv[1]) + (rowv[2] + rowv[3]))
                     + ((rowv[4] + rowv[5]) + (rowv[6] + rowv[7]));
            sS[k] = sk * 0.125f;
        } else {
            sDiag[k] = dia;
        }
        __syncthreads();

        float q = 0.f;
#pragma unroll
        for (int i = 0; i < 8; i++) q += sS[base + i];
        q *= 0.125f;

        if (h == 0) {
            const float n2 = sDiag[k] - 2.f * sS[k] + q;
            const float nr = sqrtf(fmaxf(n2, 0.f));
            sInv[k] = 1.f / fmaxf(nr, 1e-12f);
        }
        __syncthreads();

        const float sk   = sS[k];
        const float invk = sInv[k];
        float acc = 0.f;
#pragma unroll
        for (int pi = 0; pi < 2; pi++) {
            const int p = hh * 4 + h * 2 + pi;
            if (p == tgt) continue;
            const int j0 = p * 16 + s;
            const int j1 = j0 + 8;
            const float a0 = (gv0[pi] - sS[j0] - sk + q) * (sInv[j0] * invk);
            const float a1 = (gv1[pi] - sS[j1] - sk + q) * (sInv[j1] * invk);
            acc += fabsf(a0 - a1);
        }

        // Deterministic block reduction over 256 threads.
#pragma unroll
        for (int o = 16; o > 0; o >>= 1) acc += __shfl_down_sync(0xffffffffu, acc, o);
        if ((t & 31) == 0) red[t >> 5] = acc;
        __syncthreads();

        if (t == 0) {
            float sum = 0.f;
#pragma unroll
            for (int w = 0; w < 8; w++) sum += red[w];
            g_part[b] = sum;
            __threadfence();
            unsigned old = atomicAdd(&g_fin, 1u);
            sFlag[0] = ((old & (NBLOCKS - 1u)) == (NBLOCKS - 1u)) ? 1 : 0;
        }
        __syncthreads();

        // ---- parallel deterministic finalize by the last-arriving block ----
        if (sFlag[0]) {
            float v = (t < NBLOCKS) ? __ldcg(&g_part[t]) : 0.f;
#pragma unroll
            for (int o = 16; o > 0; o >>= 1) v += __shfl_down_sync(0xffffffffu, v, o);
            if ((t & 31) == 0) red[t >> 5] = v;
            __syncthreads();
            if (t == 0) {
                float tot = ((red[0] + red[1]) + (red[2] + red[3]))
                          + ((red[4] + red[5]) + (red[6] + red[7]));
                out[0] = tot * (1.0f / 114688.0f);
            }
        }
    }
}

extern "C" void kernel_launch(void* const* d_in, const int* in_sizes, int n_in,
                              void* d_out, int out_size) {
    const float* X = (const float*)d_in[0];   // [128, 2048] fp32
    float* out = (float*)d_out;               // scalar loss

    fused_angle_loss<<<NBLOCKS, NTHREADS>>>(X, out);
}